// round 2
// baseline (speedup 1.0000x reference)
#include <cuda_runtime.h>
#include <cstdint>

#define B_    8
#define N_    4096
#define FIN_  64
#define S_    1024
#define K_    64
#define H_    64
#define FOUT_ 128
#define BS_   (B_*S_)

// Scratch (device globals: no allocations allowed)
__device__ int g_samp[BS_];
__device__ int g_nbr[BS_*K_];
__device__ int g_cnt[BS_];

// Squared distance with the reference's exact f32 associativity:
// ((dx*dx + dy*dy) + dz*dz), round-to-nearest, NO fma contraction.
__device__ __forceinline__ float sqd(float ax, float ay, float az,
                                     float bx, float by, float bz) {
    float dx = __fadd_rn(ax, -bx);
    float dy = __fadd_rn(ay, -by);
    float dz = __fadd_rn(az, -bz);
    return __fadd_rn(__fadd_rn(__fmul_rn(dx, dx), __fmul_rn(dy, dy)),
                     __fmul_rn(dz, dz));
}

// ---------------------------------------------------------------------------
// Kernel 1: farthest point sampling. One block per cloud, 1024 threads,
// 4 points per thread held in registers. Argmax with first-index tie-break
// via key = (dist_bits << 32) | ~idx  (dist >= 0 so float bits are ordered).
// ---------------------------------------------------------------------------
__global__ __launch_bounds__(1024) void fps_kernel(const float* __restrict__ pos) {
    const int b = blockIdx.x;
    const int t = threadIdx.x;
    const float* P = pos + (size_t)b * N_ * 3;

    float px[4], py[4], pz[4], dist[4];
#pragma unroll
    for (int i = 0; i < 4; i++) {
        int p = (t << 2) + i;
        px[i] = P[p * 3 + 0];
        py[i] = P[p * 3 + 1];
        pz[i] = P[p * 3 + 2];
    }

    __shared__ unsigned long long warpmax[32];
    __shared__ unsigned long long winkey;

    // start point = index 0 (random_start=False)
    float nx = P[0], ny = P[1], nz = P[2];
#pragma unroll
    for (int i = 0; i < 4; i++)
        dist[i] = sqd(px[i], py[i], pz[i], nx, ny, nz);

    if (t == 0) g_samp[b * S_] = 0;

    const int lane = t & 31;
    const int wid  = t >> 5;

    for (int it = 1; it < S_; it++) {
        // local argmax over this thread's 4 points
        unsigned long long key = 0ull;
#pragma unroll
        for (int i = 0; i < 4; i++) {
            unsigned long long k =
                (((unsigned long long)__float_as_uint(dist[i])) << 32) |
                (unsigned)(0xFFFFFFFFu - (unsigned)((t << 2) + i));
            key = (key > k) ? key : k;
        }
        // warp reduce (max)
#pragma unroll
        for (int o = 16; o; o >>= 1) {
            unsigned long long ok = __shfl_xor_sync(0xFFFFFFFFu, key, o);
            key = (key > ok) ? key : ok;
        }
        if (lane == 0) warpmax[wid] = key;
        __syncthreads();
        if (wid == 0) {
            unsigned long long k2 = warpmax[lane];
#pragma unroll
            for (int o = 16; o; o >>= 1) {
                unsigned long long ok = __shfl_xor_sync(0xFFFFFFFFu, k2, o);
                k2 = (k2 > ok) ? k2 : ok;
            }
            if (lane == 0) winkey = k2;
        }
        __syncthreads();

        int widx = (int)(0xFFFFFFFFu - (unsigned)(winkey & 0xFFFFFFFFull));
        if (t == 0) g_samp[b * S_ + it] = widx;

        // winner coords: L1-resident broadcast load
        float qx = P[widx * 3 + 0];
        float qy = P[widx * 3 + 1];
        float qz = P[widx * 3 + 2];
#pragma unroll
        for (int i = 0; i < 4; i++) {
            float d2 = sqd(px[i], py[i], pz[i], qx, qy, qz);
            dist[i] = fminf(dist[i], d2);
        }
    }
}

// ---------------------------------------------------------------------------
// Kernel 2: radius ball query. One warp per centroid. Takes the FIRST K=64
// in-radius neighbors in ascending index order (matches top_k tie-breaking).
// ---------------------------------------------------------------------------
__global__ __launch_bounds__(256) void radius_kernel(const float* __restrict__ pos) {
    const int gw   = (blockIdx.x * blockDim.x + threadIdx.x) >> 5;
    const int lane = threadIdx.x & 31;
    if (gw >= BS_) return;

    const int b  = gw >> 10;  // S_ = 1024
    const int ci = g_samp[gw];
    const float* P = pos + (size_t)b * N_ * 3;
    const float cx = P[ci * 3 + 0];
    const float cy = P[ci * 3 + 1];
    const float cz = P[ci * 3 + 2];
    const float r2 = (float)(0.2 * 0.2);

    int cnt = 0;
    for (int j0 = 0; j0 < N_ && cnt < K_; j0 += 32) {
        int j = j0 + lane;
        float d2 = sqd(cx, cy, cz, P[j * 3 + 0], P[j * 3 + 1], P[j * 3 + 2]);
        bool w = (d2 <= r2);
        unsigned m = __ballot_sync(0xFFFFFFFFu, w);
        int rank = __popc(m & ((1u << lane) - 1u));
        if (w && (cnt + rank) < K_) g_nbr[gw * K_ + cnt + rank] = j;
        cnt += __popc(m);
    }
    if (lane == 0) g_cnt[gw] = (cnt < K_) ? cnt : K_;
}

// ---------------------------------------------------------------------------
// Kernel 3: message MLP + max aggregation.
// Block of 256 threads handles `cpb` centroids.
// Shared: W1 (67x64), b1, msg (64x68 padded), h1 (64x64), partials, nbr.
// W2 column (64 floats) lives in registers, loaded once per block.
// ---------------------------------------------------------------------------
__global__ __launch_bounds__(256) void mlp_kernel(
    const float* __restrict__ x, const float* __restrict__ pos,
    const float* __restrict__ W1, const float* __restrict__ b1,
    const float* __restrict__ W2, const float* __restrict__ b2,
    float* __restrict__ out, int cpb)
{
    extern __shared__ float sm[];
    float* sW1  = sm;                       // 67*64 = 4288
    float* sB1  = sW1 + 67 * 64;            // 64
    float* sMsg = sB1 + 64;                 // 64*68 = 4352 (pad 68)
    float* sH   = sMsg + 64 * 68;           // 64*64 = 4096
    float* sPart= sH + 64 * 64;             // 256
    int*   sNbr = (int*)(sPart + 256);      // 64

    const int tid = threadIdx.x;

    // stage W1 / b1
    for (int i = tid; i < 67 * 64; i += 256) sW1[i] = W1[i];
    if (tid < 64) sB1[tid] = b1[tid];

    // W2 column into registers (constant across all centroids this block does)
    const int f = tid & 127;
    float w2r[64];
#pragma unroll
    for (int h = 0; h < 64; h++) w2r[h] = W2[h * FOUT_ + f];
    const float b2r = b2[f];
    __syncthreads();

    for (int ii = 0; ii < cpb; ii++) {
        const int g  = blockIdx.x * cpb + ii;
        const int b  = g >> 10;
        const int ci = g_samp[g];
        const int c  = g_cnt[g];
        const float* P = pos + (size_t)b * N_ * 3;
        const float cx = P[ci * 3 + 0];
        const float cy = P[ci * 3 + 1];
        const float cz = P[ci * 3 + 2];

        if (tid < 64) {
            // slots >= c clamped to a valid neighbor (masked out later by c)
            sNbr[tid] = (tid < c) ? g_nbr[g * K_ + tid] : g_nbr[g * K_];
        }
        __syncthreads();

        // ---- build message [64 nbrs x 67 feats] ----
        for (int e = tid; e < 64 * 64; e += 256) {
            int n  = e >> 6;
            int cf = e & 63;
            int j  = sNbr[n];
            sMsg[n * 68 + cf] = x[((size_t)b * N_ + j) * FIN_ + cf];
        }
        if (tid < 192) {
            int n  = tid / 3;
            int cc = tid - n * 3;
            int j  = sNbr[n];
            float p  = P[j * 3 + cc];
            float c0 = (cc == 0) ? cx : ((cc == 1) ? cy : cz);
            sMsg[n * 68 + 64 + cc] = __fadd_rn(p, -c0);
        }
        __syncthreads();

        // ---- phase 1: h1[n][h] = relu(msg[n] . W1[:,h] + b1[h]) ----
        {
            const int n0 = tid >> 2;          // neighbor
            const int hb = (tid & 3) << 4;    // 16-wide h slice
            float acc[16];
#pragma unroll
            for (int u = 0; u < 16; u++) acc[u] = sB1[hb + u];
            const float4* W1v = (const float4*)sW1;
            for (int cf = 0; cf < 67; cf++) {
                float m = sMsg[n0 * 68 + cf];
#pragma unroll
                for (int q = 0; q < 4; q++) {
                    float4 w = W1v[cf * 16 + (hb >> 2) + q];
                    acc[q * 4 + 0] = __fmaf_rn(m, w.x, acc[q * 4 + 0]);
                    acc[q * 4 + 1] = __fmaf_rn(m, w.y, acc[q * 4 + 1]);
                    acc[q * 4 + 2] = __fmaf_rn(m, w.z, acc[q * 4 + 2]);
                    acc[q * 4 + 3] = __fmaf_rn(m, w.w, acc[q * 4 + 3]);
                }
            }
            float4* Hv = (float4*)(sH + n0 * 64 + hb);
#pragma unroll
            for (int q = 0; q < 4; q++) {
                float4 o;
                o.x = fmaxf(acc[q * 4 + 0], 0.f);
                o.y = fmaxf(acc[q * 4 + 1], 0.f);
                o.z = fmaxf(acc[q * 4 + 2], 0.f);
                o.w = fmaxf(acc[q * 4 + 3], 0.f);
                Hv[q] = o;
            }
        }
        __syncthreads();

        // ---- phase 2: out[f] = max_k (h1[k] . W2[:,f]) + b2[f] ----
        {
            const int kh = tid >> 7;   // two threads per f split the k range
            float best = __int_as_float(0xff800000); // -inf
            for (int k = kh; k < c; k += 2) {
                const float4* hv = (const float4*)(sH + k * 64);
                float acc = 0.f;
#pragma unroll
                for (int q = 0; q < 16; q++) {
                    float4 hh = hv[q];
                    acc = __fmaf_rn(hh.x, w2r[q * 4 + 0], acc);
                    acc = __fmaf_rn(hh.y, w2r[q * 4 + 1], acc);
                    acc = __fmaf_rn(hh.z, w2r[q * 4 + 2], acc);
                    acc = __fmaf_rn(hh.w, w2r[q * 4 + 3], acc);
                }
                best = fmaxf(best, acc);
            }
            sPart[tid] = best;
            __syncthreads();
            if (tid < 128) {
                float m = fmaxf(sPart[tid], sPart[tid + 128]);
                out[(size_t)g * FOUT_ + f] = (c > 0) ? __fadd_rn(m, b2r) : 0.0f;
            }
        }
        __syncthreads();
    }
}

// ---------------------------------------------------------------------------
// Kernel 4: gather sampled positions + batch ids into output tail.
// ---------------------------------------------------------------------------
__global__ void finalize_kernel(const float* __restrict__ pos,
                                float* __restrict__ out, int write_tail) {
    int i = blockIdx.x * blockDim.x + threadIdx.x;
    if (i >= BS_ || !write_tail) return;
    int b  = i >> 10;
    int ci = g_samp[i];
    const float* P = pos + (size_t)b * N_ * 3;
    float* pos_out = out + (size_t)BS_ * FOUT_;
    pos_out[i * 3 + 0] = P[ci * 3 + 0];
    pos_out[i * 3 + 1] = P[ci * 3 + 1];
    pos_out[i * 3 + 2] = P[ci * 3 + 2];
    out[(size_t)BS_ * FOUT_ + (size_t)BS_ * 3 + i] = (float)b;
}

// ---------------------------------------------------------------------------
extern "C" void kernel_launch(void* const* d_in, const int* in_sizes, int n_in,
                              void* d_out, int out_size) {
    const float *x = nullptr, *pos = nullptr, *W1 = nullptr, *b1 = nullptr,
                *W2 = nullptr, *b2 = nullptr;
    // Map inputs robustly by element count (all distinct).
    for (int i = 0; i < n_in; i++) {
        switch (in_sizes[i]) {
            case B_ * N_ * FIN_:  x   = (const float*)d_in[i]; break; // 2097152
            case B_ * N_ * 3:     pos = (const float*)d_in[i]; break; // 98304
            case (FIN_ + 3) * H_: W1  = (const float*)d_in[i]; break; // 4288
            case H_:              b1  = (const float*)d_in[i]; break; // 64
            case H_ * FOUT_:      W2  = (const float*)d_in[i]; break; // 8192
            case FOUT_:           b2  = (const float*)d_in[i]; break; // 128
            default: break; // batch (32768 int32) unused: reconstructed analytically
        }
    }
    float* out = (float*)d_out;

    fps_kernel<<<B_, 1024>>>(pos);
    radius_kernel<<<BS_ / 8, 256>>>(pos);

    const int smem = (67 * 64 + 64 + 64 * 68 + 64 * 64 + 256 + 64) * 4; // 52480 B
    cudaFuncSetAttribute(mlp_kernel, cudaFuncAttributeMaxDynamicSharedMemorySize, smem);
    mlp_kernel<<<1024, 256, smem>>>(x, pos, W1, b1, W2, b2, out, 8);

    const int total3 = BS_ * FOUT_ + BS_ * 3 + BS_;
    const int tail = (out_size >= total3) ? 1 : 0;
    finalize_kernel<<<(BS_ + 255) / 256, 256>>>(pos, out, tail);
}

// round 3
// speedup vs baseline: 1.3190x; 1.3190x over previous
#include <cuda_runtime.h>
#include <cstdint>

#define B_    8
#define N_    4096
#define FIN_  64
#define S_    1024
#define K_    64
#define H_    64
#define FOUT_ 128
#define BS_   (B_*S_)

// Scratch (device globals: no allocations allowed)
__device__ int g_samp[BS_];
__device__ int g_nbr[BS_*K_];
__device__ int g_cnt[BS_];

// Squared distance with the reference's exact f32 associativity:
// ((dx*dx + dy*dy) + dz*dz), round-to-nearest, NO fma contraction.
__device__ __forceinline__ float sqd(float ax, float ay, float az,
                                     float bx, float by, float bz) {
    float dx = __fadd_rn(ax, -bx);
    float dy = __fadd_rn(ay, -by);
    float dz = __fadd_rn(az, -bz);
    return __fadd_rn(__fadd_rn(__fmul_rn(dx, dx), __fmul_rn(dy, dy)),
                     __fmul_rn(dz, dz));
}

// Packed f32x2 helpers (Blackwell). Rounding is .rn, identical to scalar
// __fadd_rn/__fmul_rn, so results are bit-identical to the scalar path.
__device__ __forceinline__ unsigned long long pk2(float lo, float hi) {
    unsigned long long r;
    asm("mov.b64 %0, {%1, %2};" : "=l"(r) : "f"(lo), "f"(hi));
    return r;
}
__device__ __forceinline__ unsigned long long add2(unsigned long long a, unsigned long long b) {
    unsigned long long r;
    asm("add.rn.f32x2 %0, %1, %2;" : "=l"(r) : "l"(a), "l"(b));
    return r;
}
__device__ __forceinline__ unsigned long long mul2(unsigned long long a, unsigned long long b) {
    unsigned long long r;
    asm("mul.rn.f32x2 %0, %1, %2;" : "=l"(r) : "l"(a), "l"(b));
    return r;
}
__device__ __forceinline__ void upk2(unsigned long long p, float& lo, float& hi) {
    asm("mov.b64 {%0, %1}, %2;" : "=f"(lo), "=f"(hi) : "l"(p));
}

// ---------------------------------------------------------------------------
// Kernel 1: farthest point sampling. One block per cloud, 256 threads,
// 16 points per thread (8 packed f32x2 pairs). Positions staged in SMEM.
// Per iteration: packed distance update -> per-thread fmax tree ->
// REDUX warp max on float bits -> ballot lowest-lane -> first-index scan ->
// 8 leader keys to double-buffered SMEM -> ONE barrier -> redundant 8-way
// key max in every thread. Tie-breaks: lowest global index everywhere.
// ---------------------------------------------------------------------------
__global__ __launch_bounds__(256) void fps_kernel(const float* __restrict__ pos) {
    const int b = blockIdx.x;
    const int t = threadIdx.x;
    extern __shared__ float fsm[];
    float* sx = fsm;
    float* sy = fsm + N_;
    float* sz = fsm + 2 * N_;
    unsigned long long* skey = (unsigned long long*)(fsm + 3 * N_); // 16 (double buf)

    const float* P = pos + (size_t)b * N_ * 3;

    // Stage positions SoA into shared (coalesced global reads).
    for (int e = t; e < N_ * 3; e += 256) {
        float v = P[e];
        int p = e / 3, c = e - p * 3;
        if (c == 0) sx[p] = v; else if (c == 1) sy[p] = v; else sz[p] = v;
    }
    __syncthreads();

    // 16 points per thread, packed as 8 f32x2 pairs per coordinate.
    const int base = t * 16;
    unsigned long long px[8], py[8], pz[8];
#pragma unroll
    for (int i = 0; i < 8; i++) {
        px[i] = pk2(sx[base + 2 * i], sx[base + 2 * i + 1]);
        py[i] = pk2(sy[base + 2 * i], sy[base + 2 * i + 1]);
        pz[i] = pk2(sz[base + 2 * i], sz[base + 2 * i + 1]);
    }

    float dist[16];
    // init vs point 0
    {
        unsigned long long nqx = pk2(-sx[0], -sx[0]);
        unsigned long long nqy = pk2(-sy[0], -sy[0]);
        unsigned long long nqz = pk2(-sz[0], -sz[0]);
#pragma unroll
        for (int i = 0; i < 8; i++) {
            unsigned long long dx = add2(px[i], nqx);
            unsigned long long dy = add2(py[i], nqy);
            unsigned long long dz = add2(pz[i], nqz);
            unsigned long long s = add2(add2(mul2(dx, dx), mul2(dy, dy)), mul2(dz, dz));
            upk2(s, dist[2 * i], dist[2 * i + 1]);
        }
    }
    if (t == 0) g_samp[b * S_] = 0;

    const int lane = t & 31;
    const int wid  = t >> 5;

    for (int it = 1; it < S_; it++) {
        // per-thread max (value only), explicit tree
        float m0 = fmaxf(dist[0], dist[1]),   m1 = fmaxf(dist[2], dist[3]);
        float m2 = fmaxf(dist[4], dist[5]),   m3 = fmaxf(dist[6], dist[7]);
        float m4 = fmaxf(dist[8], dist[9]),   m5 = fmaxf(dist[10], dist[11]);
        float m6 = fmaxf(dist[12], dist[13]), m7 = fmaxf(dist[14], dist[15]);
        m0 = fmaxf(m0, m1); m2 = fmaxf(m2, m3); m4 = fmaxf(m4, m5); m6 = fmaxf(m6, m7);
        m0 = fmaxf(m0, m2); m4 = fmaxf(m4, m6);
        const float lm = fmaxf(m0, m4);

        // warp max via REDUX on monotonic bits (dist >= 0)
        const float wm = __uint_as_float(
            __reduce_max_sync(0xFFFFFFFFu, __float_as_uint(lm)));

        // lowest lane holding the max; within it, lowest point index
        unsigned ball = __ballot_sync(0xFFFFFFFFu, lm == wm);
        int src = __ffs(ball) - 1;
        int li = 0;
#pragma unroll
        for (int i = 15; i >= 0; i--) if (dist[i] == wm) li = i;
        int gidx = __shfl_sync(0xFFFFFFFFu, base + li, src);

        const int buf = (it & 1) << 3;
        if (lane == 0)
            skey[buf + wid] = (((unsigned long long)__float_as_uint(wm)) << 32)
                              | (unsigned)(0xFFFFFFFFu - (unsigned)gidx);
        __syncthreads();

        // redundant 8-way key max in every thread (no second barrier)
        unsigned long long k0 = skey[buf + 0], k1 = skey[buf + 1];
        unsigned long long k2 = skey[buf + 2], k3 = skey[buf + 3];
        unsigned long long k4 = skey[buf + 4], k5 = skey[buf + 5];
        unsigned long long k6 = skey[buf + 6], k7 = skey[buf + 7];
        k0 = (k1 > k0) ? k1 : k0;  k2 = (k3 > k2) ? k3 : k2;
        k4 = (k5 > k4) ? k5 : k4;  k6 = (k7 > k6) ? k7 : k6;
        k0 = (k2 > k0) ? k2 : k0;  k4 = (k6 > k4) ? k6 : k4;
        k0 = (k4 > k0) ? k4 : k0;
        const int widx = (int)(0xFFFFFFFFu - (unsigned)(k0 & 0xFFFFFFFFull));

        if (t == 0) g_samp[b * S_ + it] = widx;

        // winner coords: broadcast LDS
        const float qx = sx[widx], qy = sy[widx], qz = sz[widx];
        unsigned long long nqx = pk2(-qx, -qx);
        unsigned long long nqy = pk2(-qy, -qy);
        unsigned long long nqz = pk2(-qz, -qz);
#pragma unroll
        for (int i = 0; i < 8; i++) {
            unsigned long long dx = add2(px[i], nqx);
            unsigned long long dy = add2(py[i], nqy);
            unsigned long long dz = add2(pz[i], nqz);
            unsigned long long s = add2(add2(mul2(dx, dx), mul2(dy, dy)), mul2(dz, dz));
            float lo, hi;
            upk2(s, lo, hi);
            dist[2 * i]     = fminf(dist[2 * i], lo);
            dist[2 * i + 1] = fminf(dist[2 * i + 1], hi);
        }
    }
}

// ---------------------------------------------------------------------------
// Kernel 2: radius ball query. One warp per centroid. Takes the FIRST K=64
// in-radius neighbors in ascending index order (matches top_k tie-breaking).
// ---------------------------------------------------------------------------
__global__ __launch_bounds__(256) void radius_kernel(const float* __restrict__ pos) {
    const int gw   = (blockIdx.x * blockDim.x + threadIdx.x) >> 5;
    const int lane = threadIdx.x & 31;
    if (gw >= BS_) return;

    const int b  = gw >> 10;  // S_ = 1024
    const int ci = g_samp[gw];
    const float* P = pos + (size_t)b * N_ * 3;
    const float cx = P[ci * 3 + 0];
    const float cy = P[ci * 3 + 1];
    const float cz = P[ci * 3 + 2];
    const float r2 = (float)(0.2 * 0.2);

    int cnt = 0;
    for (int j0 = 0; j0 < N_ && cnt < K_; j0 += 32) {
        int j = j0 + lane;
        float d2 = sqd(cx, cy, cz, P[j * 3 + 0], P[j * 3 + 1], P[j * 3 + 2]);
        bool w = (d2 <= r2);
        unsigned m = __ballot_sync(0xFFFFFFFFu, w);
        int rank = __popc(m & ((1u << lane) - 1u));
        if (w && (cnt + rank) < K_) g_nbr[gw * K_ + cnt + rank] = j;
        cnt += __popc(m);
    }
    if (lane == 0) g_cnt[gw] = (cnt < K_) ? cnt : K_;
}

// ---------------------------------------------------------------------------
// Kernel 3: message MLP + max aggregation.
// Block of 256 threads handles `cpb` centroids.
// Shared: W1 (67x64), b1, msg (64x68 padded), h1 (64x64), partials, nbr.
// W2 column (64 floats) lives in registers, loaded once per block.
// ---------------------------------------------------------------------------
__global__ __launch_bounds__(256, 2) void mlp_kernel(
    const float* __restrict__ x, const float* __restrict__ pos,
    const float* __restrict__ W1, const float* __restrict__ b1,
    const float* __restrict__ W2, const float* __restrict__ b2,
    float* __restrict__ out, int cpb)
{
    extern __shared__ float sm[];
    float* sW1  = sm;                       // 67*64 = 4288
    float* sB1  = sW1 + 67 * 64;            // 64
    float* sMsg = sB1 + 64;                 // 64*68 = 4352 (pad 68)
    float* sH   = sMsg + 64 * 68;           // 64*64 = 4096
    float* sPart= sH + 64 * 64;             // 256
    int*   sNbr = (int*)(sPart + 256);      // 64

    const int tid = threadIdx.x;

    // stage W1 / b1
    for (int i = tid; i < 67 * 64; i += 256) sW1[i] = W1[i];
    if (tid < 64) sB1[tid] = b1[tid];

    // W2 column into registers (constant across all centroids this block does)
    const int f = tid & 127;
    float w2r[64];
#pragma unroll
    for (int h = 0; h < 64; h++) w2r[h] = W2[h * FOUT_ + f];
    const float b2r = b2[f];
    __syncthreads();

    for (int ii = 0; ii < cpb; ii++) {
        const int g  = blockIdx.x * cpb + ii;
        const int b  = g >> 10;
        const int ci = g_samp[g];
        const int c  = g_cnt[g];
        const float* P = pos + (size_t)b * N_ * 3;
        const float cx = P[ci * 3 + 0];
        const float cy = P[ci * 3 + 1];
        const float cz = P[ci * 3 + 2];

        if (tid < 64) {
            // slots >= c clamped to a valid neighbor (masked out later by c)
            sNbr[tid] = (tid < c) ? g_nbr[g * K_ + tid] : g_nbr[g * K_];
        }
        __syncthreads();

        // ---- build message [64 nbrs x 67 feats] ----
        for (int e = tid; e < 64 * 64; e += 256) {
            int n  = e >> 6;
            int cf = e & 63;
            int j  = sNbr[n];
            sMsg[n * 68 + cf] = x[((size_t)b * N_ + j) * FIN_ + cf];
        }
        if (tid < 192) {
            int n  = tid / 3;
            int cc = tid - n * 3;
            int j  = sNbr[n];
            float p  = P[j * 3 + cc];
            float c0 = (cc == 0) ? cx : ((cc == 1) ? cy : cz);
            sMsg[n * 68 + 64 + cc] = __fadd_rn(p, -c0);
        }
        __syncthreads();

        // ---- phase 1: h1[n][h] = relu(msg[n] . W1[:,h] + b1[h]) ----
        {
            const int n0 = tid >> 2;          // neighbor
            const int hb = (tid & 3) << 4;    // 16-wide h slice
            float acc[16];
#pragma unroll
            for (int u = 0; u < 16; u++) acc[u] = sB1[hb + u];
            const float4* W1v = (const float4*)sW1;
            for (int cf = 0; cf < 67; cf++) {
                float m = sMsg[n0 * 68 + cf];
#pragma unroll
                for (int q = 0; q < 4; q++) {
                    float4 w = W1v[cf * 16 + (hb >> 2) + q];
                    acc[q * 4 + 0] = __fmaf_rn(m, w.x, acc[q * 4 + 0]);
                    acc[q * 4 + 1] = __fmaf_rn(m, w.y, acc[q * 4 + 1]);
                    acc[q * 4 + 2] = __fmaf_rn(m, w.z, acc[q * 4 + 2]);
                    acc[q * 4 + 3] = __fmaf_rn(m, w.w, acc[q * 4 + 3]);
                }
            }
            float4* Hv = (float4*)(sH + n0 * 64 + hb);
#pragma unroll
            for (int q = 0; q < 4; q++) {
                float4 o;
                o.x = fmaxf(acc[q * 4 + 0], 0.f);
                o.y = fmaxf(acc[q * 4 + 1], 0.f);
                o.z = fmaxf(acc[q * 4 + 2], 0.f);
                o.w = fmaxf(acc[q * 4 + 3], 0.f);
                Hv[q] = o;
            }
        }
        __syncthreads();

        // ---- phase 2: out[f] = max_k (h1[k] . W2[:,f]) + b2[f] ----
        {
            const int kh = tid >> 7;   // two threads per f split the k range
            float best = __int_as_float(0xff800000); // -inf
            for (int k = kh; k < c; k += 2) {
                const float4* hv = (const float4*)(sH + k * 64);
                float acc = 0.f;
#pragma unroll
                for (int q = 0; q < 16; q++) {
                    float4 hh = hv[q];
                    acc = __fmaf_rn(hh.x, w2r[q * 4 + 0], acc);
                    acc = __fmaf_rn(hh.y, w2r[q * 4 + 1], acc);
                    acc = __fmaf_rn(hh.z, w2r[q * 4 + 2], acc);
                    acc = __fmaf_rn(hh.w, w2r[q * 4 + 3], acc);
                }
                best = fmaxf(best, acc);
            }
            sPart[tid] = best;
            __syncthreads();
            if (tid < 128) {
                float m = fmaxf(sPart[tid], sPart[tid + 128]);
                out[(size_t)g * FOUT_ + f] = (c > 0) ? __fadd_rn(m, b2r) : 0.0f;
            }
        }
        __syncthreads();
    }
}

// ---------------------------------------------------------------------------
// Kernel 4: gather sampled positions + batch ids into output tail.
// ---------------------------------------------------------------------------
__global__ void finalize_kernel(const float* __restrict__ pos,
                                float* __restrict__ out, int write_tail) {
    int i = blockIdx.x * blockDim.x + threadIdx.x;
    if (i >= BS_ || !write_tail) return;
    int b  = i >> 10;
    int ci = g_samp[i];
    const float* P = pos + (size_t)b * N_ * 3;
    float* pos_out = out + (size_t)BS_ * FOUT_;
    pos_out[i * 3 + 0] = P[ci * 3 + 0];
    pos_out[i * 3 + 1] = P[ci * 3 + 1];
    pos_out[i * 3 + 2] = P[ci * 3 + 2];
    out[(size_t)BS_ * FOUT_ + (size_t)BS_ * 3 + i] = (float)b;
}

// ---------------------------------------------------------------------------
extern "C" void kernel_launch(void* const* d_in, const int* in_sizes, int n_in,
                              void* d_out, int out_size) {
    const float *x = nullptr, *pos = nullptr, *W1 = nullptr, *b1 = nullptr,
                *W2 = nullptr, *b2 = nullptr;
    // Map inputs robustly by element count (all distinct).
    for (int i = 0; i < n_in; i++) {
        switch (in_sizes[i]) {
            case B_ * N_ * FIN_:  x   = (const float*)d_in[i]; break; // 2097152
            case B_ * N_ * 3:     pos = (const float*)d_in[i]; break; // 98304
            case (FIN_ + 3) * H_: W1  = (const float*)d_in[i]; break; // 4288
            case H_:              b1  = (const float*)d_in[i]; break; // 64
            case H_ * FOUT_:      W2  = (const float*)d_in[i]; break; // 8192
            case FOUT_:           b2  = (const float*)d_in[i]; break; // 128
            default: break; // batch (32768 int32) unused: reconstructed analytically
        }
    }
    float* out = (float*)d_out;

    const int fps_smem = (3 * N_) * 4 + 16 * 8; // 49280 B
    cudaFuncSetAttribute(fps_kernel, cudaFuncAttributeMaxDynamicSharedMemorySize, fps_smem);
    fps_kernel<<<B_, 256, fps_smem>>>(pos);

    radius_kernel<<<BS_ / 8, 256>>>(pos);

    const int smem = (67 * 64 + 64 + 64 * 68 + 64 * 64 + 256 + 64) * 4; // 52480 B
    cudaFuncSetAttribute(mlp_kernel, cudaFuncAttributeMaxDynamicSharedMemorySize, smem);
    mlp_kernel<<<2048, 256, smem>>>(x, pos, W1, b1, W2, b2, out, 4);

    const int total3 = BS_ * FOUT_ + BS_ * 3 + BS_;
    const int tail = (out_size >= total3) ? 1 : 0;
    finalize_kernel<<<(BS_ + 255) / 256, 256>>>(pos, out, tail);
}

// round 4
// speedup vs baseline: 1.4967x; 1.1347x over previous
#include <cuda_runtime.h>
#include <cstdint>

#define B_    8
#define N_    4096
#define FIN_  64
#define S_    1024
#define K_    64
#define H_    64
#define FOUT_ 128
#define BS_   (B_*S_)
#define PSTR  32          // g_prog padding: 32 ints = 128B per cloud
#define NHALF 280         // 140 worker blocks x 2 halves

typedef unsigned long long ull;

// Scratch (device globals: no allocations allowed)
__device__ int g_samp[BS_];
__device__ __align__(128) int g_prog[B_ * PSTR];   // zero-init at module load

// Squared distance with the reference's exact f32 associativity:
// ((dx*dx + dy*dy) + dz*dz), round-to-nearest, NO fma contraction.
__device__ __forceinline__ float sqd(float ax, float ay, float az,
                                     float bx, float by, float bz) {
    float dx = __fadd_rn(ax, -bx);
    float dy = __fadd_rn(ay, -by);
    float dz = __fadd_rn(az, -bz);
    return __fadd_rn(__fadd_rn(__fmul_rn(dx, dx), __fmul_rn(dy, dy)),
                     __fmul_rn(dz, dz));
}

// Packed f32x2 helpers. Per-lane rounding identical to scalar __fadd_rn etc.
__device__ __forceinline__ ull pk2(float lo, float hi) {
    ull r; asm("mov.b64 %0, {%1, %2};" : "=l"(r) : "f"(lo), "f"(hi)); return r;
}
__device__ __forceinline__ ull add2(ull a, ull b) {
    ull r; asm("add.rn.f32x2 %0, %1, %2;" : "=l"(r) : "l"(a), "l"(b)); return r;
}
__device__ __forceinline__ ull mul2(ull a, ull b) {
    ull r; asm("mul.rn.f32x2 %0, %1, %2;" : "=l"(r) : "l"(a), "l"(b)); return r;
}
__device__ __forceinline__ ull fma2(ull a, ull b, ull c) {
    ull r; asm("fma.rn.f32x2 %0, %1, %2, %3;" : "=l"(r) : "l"(a), "l"(b), "l"(c)); return r;
}
__device__ __forceinline__ void upk2(ull p, float& lo, float& hi) {
    asm("mov.b64 {%0, %1}, %2;" : "=f"(lo), "=f"(hi) : "l"(p));
}

// Release/acquire for the FPS -> worker handoff.
__device__ __forceinline__ void st_release(int* p, int v) {
    asm volatile("st.release.gpu.global.s32 [%0], %1;" :: "l"(p), "r"(v) : "memory");
}
__device__ __forceinline__ int ld_acquire(const int* p) {
    int v;
    asm volatile("ld.acquire.gpu.global.s32 %0, [%1];" : "=r"(v) : "l"(p) : "memory");
    return v;
}

#define BAR(id) asm volatile("bar.sync %0, %1;" :: "r"(id), "r"(256) : "memory")

// ---------------------------------------------------------------------------
// FPS role: one block per cloud, 512 threads, 8 points per thread
// (4 packed f32x2 pairs). Publishes g_samp progressively via release stores.
// Tie-breaks: lowest index everywhere. Numerics identical to Round-3 version.
// ---------------------------------------------------------------------------
__device__ void fps_role(const float* __restrict__ pos, int b, float* fsm) {
    const int t = threadIdx.x;
    float* sx = fsm;
    float* sy = fsm + N_;
    float* sz = fsm + 2 * N_;
    ull* skey = (ull*)(fsm + 3 * N_);   // 32 entries (16 warps, double buffered)

    const float* P = pos + (size_t)b * N_ * 3;
    int* prog = &g_prog[b * PSTR];

    for (int e = t; e < N_ * 3; e += 512) {
        float v = P[e];
        int p = e / 3, c = e - p * 3;
        if (c == 0) sx[p] = v; else if (c == 1) sy[p] = v; else sz[p] = v;
    }
    __syncthreads();

    const int base = t * 8;
    ull px[4], py[4], pz[4];
#pragma unroll
    for (int i = 0; i < 4; i++) {
        px[i] = pk2(sx[base + 2 * i], sx[base + 2 * i + 1]);
        py[i] = pk2(sy[base + 2 * i], sy[base + 2 * i + 1]);
        pz[i] = pk2(sz[base + 2 * i], sz[base + 2 * i + 1]);
    }

    float dist[8];
    {
        ull nqx = pk2(-sx[0], -sx[0]);
        ull nqy = pk2(-sy[0], -sy[0]);
        ull nqz = pk2(-sz[0], -sz[0]);
#pragma unroll
        for (int i = 0; i < 4; i++) {
            ull dx = add2(px[i], nqx);
            ull dy = add2(py[i], nqy);
            ull dz = add2(pz[i], nqz);
            ull s = add2(add2(mul2(dx, dx), mul2(dy, dy)), mul2(dz, dz));
            upk2(s, dist[2 * i], dist[2 * i + 1]);
        }
    }
    if (t == 0) { g_samp[b * S_] = 0; st_release(prog, 1); }

    const int lane = t & 31;
    const int wid  = t >> 5;

    for (int it = 1; it < S_; it++) {
        float m0 = fmaxf(dist[0], dist[1]), m1 = fmaxf(dist[2], dist[3]);
        float m2 = fmaxf(dist[4], dist[5]), m3 = fmaxf(dist[6], dist[7]);
        m0 = fmaxf(m0, m1); m2 = fmaxf(m2, m3);
        const float lm = fmaxf(m0, m2);

        const float wm = __uint_as_float(
            __reduce_max_sync(0xFFFFFFFFu, __float_as_uint(lm)));

        unsigned ball = __ballot_sync(0xFFFFFFFFu, lm == wm);
        int src = __ffs(ball) - 1;
        int li = 0;
#pragma unroll
        for (int i = 7; i >= 0; i--) if (dist[i] == wm) li = i;
        int gidx = __shfl_sync(0xFFFFFFFFu, base + li, src);

        const int buf = (it & 1) << 4;
        if (lane == 0)
            skey[buf + wid] = (((ull)__float_as_uint(wm)) << 32)
                              | (unsigned)(0xFFFFFFFFu - (unsigned)gidx);
        __syncthreads();

        ull k0 = skey[buf + 0],  k1 = skey[buf + 1];
        ull k2 = skey[buf + 2],  k3 = skey[buf + 3];
        ull k4 = skey[buf + 4],  k5 = skey[buf + 5];
        ull k6 = skey[buf + 6],  k7 = skey[buf + 7];
        ull k8 = skey[buf + 8],  k9 = skey[buf + 9];
        ull ka = skey[buf + 10], kb = skey[buf + 11];
        ull kc = skey[buf + 12], kd = skey[buf + 13];
        ull ke = skey[buf + 14], kf = skey[buf + 15];
        k0 = (k1 > k0) ? k1 : k0;  k2 = (k3 > k2) ? k3 : k2;
        k4 = (k5 > k4) ? k5 : k4;  k6 = (k7 > k6) ? k7 : k6;
        k8 = (k9 > k8) ? k9 : k8;  ka = (kb > ka) ? kb : ka;
        kc = (kd > kc) ? kd : kc;  ke = (kf > ke) ? kf : ke;
        k0 = (k2 > k0) ? k2 : k0;  k4 = (k6 > k4) ? k6 : k4;
        k8 = (ka > k8) ? ka : k8;  kc = (ke > kc) ? ke : kc;
        k0 = (k4 > k0) ? k4 : k0;  k8 = (kc > k8) ? kc : k8;
        k0 = (k8 > k0) ? k8 : k0;
        const int widx = (int)(0xFFFFFFFFu - (unsigned)(k0 & 0xFFFFFFFFull));

        if (t == 0) { g_samp[b * S_ + it] = widx; st_release(prog, it + 1); }

        const float qx = sx[widx], qy = sy[widx], qz = sz[widx];
        ull nqx = pk2(-qx, -qx);
        ull nqy = pk2(-qy, -qy);
        ull nqz = pk2(-qz, -qz);
#pragma unroll
        for (int i = 0; i < 4; i++) {
            ull dx = add2(px[i], nqx);
            ull dy = add2(py[i], nqy);
            ull dz = add2(pz[i], nqz);
            ull s = add2(add2(mul2(dx, dx), mul2(dy, dy)), mul2(dz, dz));
            float lo, hi;
            upk2(s, lo, hi);
            dist[2 * i]     = fminf(dist[2 * i], lo);
            dist[2 * i + 1] = fminf(dist[2 * i + 1], hi);
        }
    }
}

// ---------------------------------------------------------------------------
// Fused kernel: blocks 0..7 = FPS, blocks 8..147 = workers.
// Each worker block = two independent 256-thread halves (named barriers).
// Half processes batches of 8 centroids (same s, clouds 0..7):
//   poll FPS progress -> radius (warp per cloud, lists in SMEM) -> MLP+max.
// ---------------------------------------------------------------------------
// Worker half SMEM region layout (floats, relative):
//   0    : sMsg [64*68]
//   4352 : sH   [64*64]
//   8448 : sPart[256]
//   8704 : snbr (int)[8*64]
//   9216 : scnt (int)[8]
//   9224 : scx[8]  9232: scy[8]  9240: scz[8]
//   total 9248
#define HALF_FLOATS 9248
#define SMEM_FLOATS (67*64 + 64 + 2*HALF_FLOATS)   // 22848 floats = 91392 B

__global__ __launch_bounds__(512, 1) void sa_fused_kernel(
    const float* __restrict__ x, const float* __restrict__ pos,
    const float* __restrict__ W1, const float* __restrict__ b1,
    const float* __restrict__ W2, const float* __restrict__ b2,
    float* __restrict__ out, int write_tail)
{
    extern __shared__ float sm[];
    const int bid = blockIdx.x;

    if (bid < B_) { fps_role(pos, bid, sm); return; }

    // ---------------- worker ----------------
    const int tid = threadIdx.x;
    float* sW1 = sm;                 // 4288
    float* sB1 = sm + 67 * 64;       // 64

    for (int i = tid; i < 67 * 64; i += 512) sW1[i] = W1[i];
    if (tid < 64) sB1[tid] = b1[tid];
    __syncthreads();   // only block-wide sync in the worker path

    const int half = tid >> 8;       // 0 / 1
    const int tl   = tid & 255;
    const int barid = 1 + half;
    float* R    = sm + 67 * 64 + 64 + half * HALF_FLOATS;
    float* sMsg = R;
    float* sH   = R + 4352;
    float* sPart= R + 8448;
    int*   snbr = (int*)(R + 8704);
    int*   scnt = (int*)(R + 9216);
    float* scx  = R + 9224;
    float* scy  = R + 9232;
    float* scz  = R + 9240;

    const int hw   = (bid - B_) * 2 + half;   // 0..279
    const int lane = tl & 31;
    const int wl   = tl >> 5;                 // warp-in-half = cloud id

    // W2 column into registers (per-thread f)
    const int f = tl & 127;
    float w2r[64];
#pragma unroll
    for (int h = 0; h < 64; h++) w2r[h] = W2[h * FOUT_ + f];
    const float b2r = b2[f];

    const float r2 = (float)(0.2 * 0.2);
    float* tail_pos = out + (size_t)BS_ * FOUT_;
    float* tail_bat = out + (size_t)BS_ * FOUT_ + (size_t)BS_ * 3;

    for (int sidx = hw; sidx < S_; sidx += NHALF) {
        BAR(barid);   // protect smem from previous batch's laggards

        // ---- radius: warp wl handles cloud b = wl, centroid sample sidx ----
        {
            const int b = wl;
            if (lane == 0) {
                while (ld_acquire(&g_prog[b * PSTR]) <= sidx) __nanosleep(200);
            }
            __syncwarp();
            const int ci = __ldcg(&g_samp[b * S_ + sidx]);
            const float* P = pos + (size_t)b * N_ * 3;
            const float cx = P[ci * 3 + 0];
            const float cy = P[ci * 3 + 1];
            const float cz = P[ci * 3 + 2];

            int cnt = 0;
            for (int j0 = 0; j0 < N_ && cnt < K_; j0 += 32) {
                int j = j0 + lane;
                float d2 = sqd(cx, cy, cz, P[j*3+0], P[j*3+1], P[j*3+2]);
                bool w = (d2 <= r2);
                unsigned m = __ballot_sync(0xFFFFFFFFu, w);
                int rank = __popc(m & ((1u << lane) - 1u));
                if (w && (cnt + rank) < K_) snbr[wl * K_ + cnt + rank] = j;
                cnt += __popc(m);
            }
            if (lane == 0) {
                scnt[wl] = (cnt < K_) ? cnt : K_;
                scx[wl] = cx; scy[wl] = cy; scz[wl] = cz;
            }
        }
        BAR(barid);

        // ---- MLP + max for the 8 centroids of this batch ----
        for (int j = 0; j < 8; j++) {
            const int b = j;
            const int c = scnt[j];
            const int g = b * S_ + sidx;
            const float cx = scx[j], cy = scy[j], cz = scz[j];
            const float* P = pos + (size_t)b * N_ * 3;

            // message build [64 nbrs x 67 feats]
            for (int e = tl; e < 64 * 64; e += 256) {
                int n  = e >> 6;
                int cf = e & 63;
                int jn = (n < c) ? snbr[j * K_ + n] : snbr[j * K_];
                sMsg[n * 68 + cf] = x[((size_t)b * N_ + jn) * FIN_ + cf];
            }
            if (tl < 192) {
                int n  = tl / 3;
                int cc = tl - n * 3;
                int jn = (n < c) ? snbr[j * K_ + n] : snbr[j * K_];
                float p  = P[jn * 3 + cc];
                float c0 = (cc == 0) ? cx : ((cc == 1) ? cy : cz);
                sMsg[n * 68 + 64 + cc] = __fadd_rn(p, -c0);
            }
            BAR(barid);

            // phase 1 (packed f32x2, bit-identical to scalar chain):
            // h1[n][h] = relu(msg[n] . W1[:,h] + b1[h])
            {
                const int n0 = tl >> 2;
                const int hb = (tl & 3) << 4;
                ull acc2[8];
#pragma unroll
                for (int u = 0; u < 8; u++)
                    acc2[u] = pk2(sB1[hb + 2*u], sB1[hb + 2*u + 1]);
                const ull* W1p = (const ull*)sW1;   // 2 floats per entry
                for (int cf = 0; cf < 67; cf++) {
                    float m = sMsg[n0 * 68 + cf];
                    ull mm = pk2(m, m);
                    const ull* wrow = W1p + cf * 32 + (hb >> 1);
#pragma unroll
                    for (int u = 0; u < 8; u++)
                        acc2[u] = fma2(mm, wrow[u], acc2[u]);
                }
#pragma unroll
                for (int u = 0; u < 8; u++) {
                    float lo, hi;
                    upk2(acc2[u], lo, hi);
                    float2 o;
                    o.x = fmaxf(lo, 0.f);
                    o.y = fmaxf(hi, 0.f);
                    *(float2*)&sH[n0 * 64 + hb + 2*u] = o;
                }
            }
            BAR(barid);

            // phase 2: out[f] = max_k (h1[k] . W2[:,f]) + b2[f]
            {
                const int kh = tl >> 7;
                float best = __int_as_float(0xff800000);
                for (int k = kh; k < c; k += 2) {
                    const float4* hv = (const float4*)(sH + k * 64);
                    float acc = 0.f;
#pragma unroll
                    for (int q = 0; q < 16; q++) {
                        float4 hh = hv[q];
                        acc = __fmaf_rn(hh.x, w2r[q*4+0], acc);
                        acc = __fmaf_rn(hh.y, w2r[q*4+1], acc);
                        acc = __fmaf_rn(hh.z, w2r[q*4+2], acc);
                        acc = __fmaf_rn(hh.w, w2r[q*4+3], acc);
                    }
                    best = fmaxf(best, acc);
                }
                sPart[tl] = best;
                BAR(barid);
                if (tl < 128) {
                    float m = fmaxf(sPart[tl], sPart[tl + 128]);
                    out[(size_t)g * FOUT_ + f] = (c > 0) ? __fadd_rn(m, b2r) : 0.0f;
                }
                if (write_tail && tl >= 252) {
                    int c3 = tl - 252;
                    if      (c3 == 0) tail_pos[g * 3 + 0] = cx;
                    else if (c3 == 1) tail_pos[g * 3 + 1] = cy;
                    else if (c3 == 2) tail_pos[g * 3 + 2] = cz;
                    else              tail_bat[g] = (float)b;
                }
            }
            BAR(barid);
        }
    }
}

// ---------------------------------------------------------------------------
extern "C" void kernel_launch(void* const* d_in, const int* in_sizes, int n_in,
                              void* d_out, int out_size) {
    const float *x = nullptr, *pos = nullptr, *W1 = nullptr, *b1 = nullptr,
                *W2 = nullptr, *b2 = nullptr;
    for (int i = 0; i < n_in; i++) {
        switch (in_sizes[i]) {
            case B_ * N_ * FIN_:  x   = (const float*)d_in[i]; break;
            case B_ * N_ * 3:     pos = (const float*)d_in[i]; break;
            case (FIN_ + 3) * H_: W1  = (const float*)d_in[i]; break;
            case H_:              b1  = (const float*)d_in[i]; break;
            case H_ * FOUT_:      W2  = (const float*)d_in[i]; break;
            case FOUT_:           b2  = (const float*)d_in[i]; break;
            default: break; // batch ids reconstructed analytically
        }
    }
    float* out = (float*)d_out;

    const int total3 = BS_ * FOUT_ + BS_ * 3 + BS_;
    const int tail = (out_size >= total3) ? 1 : 0;

    const int smem = SMEM_FLOATS * 4;   // 91392 B
    cudaFuncSetAttribute(sa_fused_kernel,
                         cudaFuncAttributeMaxDynamicSharedMemorySize, smem);
    sa_fused_kernel<<<B_ + 140, 512, smem>>>(x, pos, W1, b1, W2, b2, out, tail);
}

// round 9
// speedup vs baseline: 1.9410x; 1.2969x over previous
#include <cuda_runtime.h>
#include <cstdint>

#define B_    8
#define N_    4096
#define FIN_  64
#define S_    1024
#define K_    64
#define H_    64
#define FOUT_ 128
#define BS_   (B_*S_)

typedef unsigned long long ull;

// Scratch (device globals: no allocations allowed). All fully overwritten
// every run -> replay-deterministic without any reset.
__device__ int g_samp[BS_];
__device__ int g_nbr[BS_*K_];
__device__ int g_cnt[BS_];
// 16B alignment REQUIRED: accessed via ulonglong2/float2 vector ld/st.
__device__ __align__(16) float g_U[(size_t)B_ * N_ * H_];   // U'[j] = b1 + x_j @ W1[0:64]

// Squared distance with the reference's exact f32 associativity.
__device__ __forceinline__ float sqd(float ax, float ay, float az,
                                     float bx, float by, float bz) {
    float dx = __fadd_rn(ax, -bx);
    float dy = __fadd_rn(ay, -by);
    float dz = __fadd_rn(az, -bz);
    return __fadd_rn(__fadd_rn(__fmul_rn(dx, dx), __fmul_rn(dy, dy)),
                     __fmul_rn(dz, dz));
}

// Packed f32x2 helpers. Per-lane rounding identical to scalar __fadd_rn etc.
__device__ __forceinline__ ull pk2(float lo, float hi) {
    ull r; asm("mov.b64 %0, {%1, %2};" : "=l"(r) : "f"(lo), "f"(hi)); return r;
}
__device__ __forceinline__ ull add2(ull a, ull b) {
    ull r; asm("add.rn.f32x2 %0, %1, %2;" : "=l"(r) : "l"(a), "l"(b)); return r;
}
__device__ __forceinline__ ull mul2(ull a, ull b) {
    ull r; asm("mul.rn.f32x2 %0, %1, %2;" : "=l"(r) : "l"(a), "l"(b)); return r;
}
__device__ __forceinline__ ull fma2(ull a, ull b, ull c) {
    ull r; asm("fma.rn.f32x2 %0, %1, %2, %3;" : "=l"(r) : "l"(a), "l"(b), "l"(c)); return r;
}
__device__ __forceinline__ void upk2(ull p, float& lo, float& hi) {
    asm("mov.b64 {%0, %1}, %2;" : "=f"(lo), "=f"(hi) : "l"(p));
}

// ---------------------------------------------------------------------------
// Kernel A: U'[j][h] = b1[h] + sum_{cf=0..63} x[j][cf] * W1[cf][h]
// Same op order as the proven bit-exact phase-1 prefix.
// ---------------------------------------------------------------------------
__global__ __launch_bounds__(256) void u_kernel(
    const float* __restrict__ x, const float* __restrict__ W1,
    const float* __restrict__ b1)
{
    __shared__ __align__(16) float sW[64 * 64];    // W1 rows 0..63
    __shared__ __align__(16) float sB[64];
    __shared__ __align__(16) float sX[64 * 68];    // 64 rows of x, padded

    const int tid = threadIdx.x;
    const int r0  = blockIdx.x * 64;

    for (int i = tid; i < 64 * 64; i += 256) sW[i] = W1[i];
    if (tid < 64) sB[tid] = b1[tid];
    for (int e = tid; e < 64 * 64; e += 256) {
        int row = e >> 6, cf = e & 63;
        sX[row * 68 + cf] = x[(size_t)(r0 + row) * FIN_ + cf];
    }
    __syncthreads();

    const int n0 = tid >> 2;
    const int hb = (tid & 3) << 4;

    ull acc2[8];
#pragma unroll
    for (int u = 0; u < 8; u++)
        acc2[u] = pk2(sB[hb + 2 * u], sB[hb + 2 * u + 1]);

    const ull* Wp = (const ull*)sW;
    for (int cf = 0; cf < 64; cf++) {
        float m = sX[n0 * 68 + cf];
        ull mm = pk2(m, m);
        const ull* wrow = Wp + cf * 32 + (hb >> 1);
#pragma unroll
        for (int u = 0; u < 8; u++)
            acc2[u] = fma2(mm, wrow[u], acc2[u]);
    }

    float* Urow = g_U + (size_t)(r0 + n0) * H_ + hb;
#pragma unroll
    for (int u = 0; u < 8; u++) {
        float lo, hi;
        upk2(acc2[u], lo, hi);
        float2 o; o.x = lo; o.y = hi;
        *(float2*)(Urow + 2 * u) = o;
    }
}

// ---------------------------------------------------------------------------
// Kernel B: farthest point sampling. One block per cloud, 512 threads,
// 8 points per thread. Plain g_samp stores; kernel boundary is the sync.
// Bit-exact numerics (proven inside the R4 fused kernel).
// ---------------------------------------------------------------------------
__global__ __launch_bounds__(512) void fps_kernel(const float* __restrict__ pos) {
    extern __shared__ __align__(16) float fsm[];
    const int b = blockIdx.x;
    const int t = threadIdx.x;
    float* sx = fsm;
    float* sy = fsm + N_;
    float* sz = fsm + 2 * N_;
    ull* skey = (ull*)(fsm + 3 * N_);   // 32 entries (16 warps, double buffered)

    const float* P = pos + (size_t)b * N_ * 3;

    for (int e = t; e < N_ * 3; e += 512) {
        float v = P[e];
        int p = e / 3, c = e - p * 3;
        if (c == 0) sx[p] = v; else if (c == 1) sy[p] = v; else sz[p] = v;
    }
    __syncthreads();

    const int base = t * 8;
    ull px[4], py[4], pz[4];
#pragma unroll
    for (int i = 0; i < 4; i++) {
        px[i] = pk2(sx[base + 2 * i], sx[base + 2 * i + 1]);
        py[i] = pk2(sy[base + 2 * i], sy[base + 2 * i + 1]);
        pz[i] = pk2(sz[base + 2 * i], sz[base + 2 * i + 1]);
    }

    float dist[8];
    {
        ull nqx = pk2(-sx[0], -sx[0]);
        ull nqy = pk2(-sy[0], -sy[0]);
        ull nqz = pk2(-sz[0], -sz[0]);
#pragma unroll
        for (int i = 0; i < 4; i++) {
            ull dx = add2(px[i], nqx);
            ull dy = add2(py[i], nqy);
            ull dz = add2(pz[i], nqz);
            ull s = add2(add2(mul2(dx, dx), mul2(dy, dy)), mul2(dz, dz));
            upk2(s, dist[2 * i], dist[2 * i + 1]);
        }
    }
    if (t == 0) g_samp[b * S_] = 0;

    const int lane = t & 31;
    const int wid  = t >> 5;

    for (int it = 1; it < S_; it++) {
        float m0 = fmaxf(dist[0], dist[1]), m1 = fmaxf(dist[2], dist[3]);
        float m2 = fmaxf(dist[4], dist[5]), m3 = fmaxf(dist[6], dist[7]);
        m0 = fmaxf(m0, m1); m2 = fmaxf(m2, m3);
        const float lm = fmaxf(m0, m2);

        const float wm = __uint_as_float(
            __reduce_max_sync(0xFFFFFFFFu, __float_as_uint(lm)));

        unsigned ball = __ballot_sync(0xFFFFFFFFu, lm == wm);
        int src = __ffs(ball) - 1;
        int li = 0;
#pragma unroll
        for (int i = 7; i >= 0; i--) if (dist[i] == wm) li = i;
        int gidx = __shfl_sync(0xFFFFFFFFu, base + li, src);

        const int buf = (it & 1) << 4;
        if (lane == 0)
            skey[buf + wid] = (((ull)__float_as_uint(wm)) << 32)
                              | (unsigned)(0xFFFFFFFFu - (unsigned)gidx);
        __syncthreads();

        ull k0 = skey[buf + 0],  k1 = skey[buf + 1];
        ull k2 = skey[buf + 2],  k3 = skey[buf + 3];
        ull k4 = skey[buf + 4],  k5 = skey[buf + 5];
        ull k6 = skey[buf + 6],  k7 = skey[buf + 7];
        ull k8 = skey[buf + 8],  k9 = skey[buf + 9];
        ull ka = skey[buf + 10], kb = skey[buf + 11];
        ull kc = skey[buf + 12], kd = skey[buf + 13];
        ull ke = skey[buf + 14], kf = skey[buf + 15];
        k0 = (k1 > k0) ? k1 : k0;  k2 = (k3 > k2) ? k3 : k2;
        k4 = (k5 > k4) ? k5 : k4;  k6 = (k7 > k6) ? k7 : k6;
        k8 = (k9 > k8) ? k9 : k8;  ka = (kb > ka) ? kb : ka;
        kc = (kd > kc) ? kd : kc;  ke = (kf > ke) ? kf : ke;
        k0 = (k2 > k0) ? k2 : k0;  k4 = (k6 > k4) ? k6 : k4;
        k8 = (ka > k8) ? ka : k8;  kc = (ke > kc) ? ke : kc;
        k0 = (k4 > k0) ? k4 : k0;  k8 = (kc > k8) ? kc : k8;
        k0 = (k8 > k0) ? k8 : k0;
        const int widx =
            ((int)(0xFFFFFFFFu - (unsigned)(k0 & 0xFFFFFFFFull))) & (N_ - 1);

        if (t == 0) g_samp[b * S_ + it] = widx;

        const float qx = sx[widx], qy = sy[widx], qz = sz[widx];
        ull nqx = pk2(-qx, -qx);
        ull nqy = pk2(-qy, -qy);
        ull nqz = pk2(-qz, -qz);
#pragma unroll
        for (int i = 0; i < 4; i++) {
            ull dx = add2(px[i], nqx);
            ull dy = add2(py[i], nqy);
            ull dz = add2(pz[i], nqz);
            ull s = add2(add2(mul2(dx, dx), mul2(dy, dy)), mul2(dz, dz));
            float lo, hi;
            upk2(s, lo, hi);
            dist[2 * i]     = fminf(dist[2 * i], lo);
            dist[2 * i + 1] = fminf(dist[2 * i + 1], hi);
        }
    }
}

// ---------------------------------------------------------------------------
// Kernel C: radius ball query. One warp per centroid; FIRST K=64 in-radius
// neighbors in ascending index order (matches top_k tie-breaking). Proven.
// ---------------------------------------------------------------------------
__global__ __launch_bounds__(256) void radius_kernel(const float* __restrict__ pos) {
    const int gw   = (blockIdx.x * blockDim.x + threadIdx.x) >> 5;
    const int lane = threadIdx.x & 31;
    if (gw >= BS_) return;

    const int b  = gw >> 10;  // S_ = 1024
    const int ci = g_samp[gw];
    const float* P = pos + (size_t)b * N_ * 3;
    const float cx = P[ci * 3 + 0];
    const float cy = P[ci * 3 + 1];
    const float cz = P[ci * 3 + 2];
    const float r2 = (float)(0.2 * 0.2);

    int cnt = 0;
    for (int j0 = 0; j0 < N_ && cnt < K_; j0 += 32) {
        int j = j0 + lane;
        float d2 = sqd(cx, cy, cz, P[j * 3 + 0], P[j * 3 + 1], P[j * 3 + 2]);
        bool w = (d2 <= r2);
        unsigned m = __ballot_sync(0xFFFFFFFFu, w);
        int rank = __popc(m & ((1u << lane) - 1u));
        if (w && (cnt + rank) < K_) g_nbr[gw * K_ + cnt + rank] = j;
        cnt += __popc(m);
    }
    if (lane == 0) g_cnt[gw] = (cnt < K_) ? cnt : K_;
}

// ---------------------------------------------------------------------------
// Kernel D: MLP + max aggregation with hoisted U'. 256 threads, 8 centroids
// per block. Phase 1: h1[n] = relu(U'[jn] + dp . W1[64:67]). Phase 2: packed
// f32x2 dot with W2 column held in registers. Tail writes folded in.
// ---------------------------------------------------------------------------
__global__ __launch_bounds__(256) void mlp_kernel(
    const float* __restrict__ pos, const float* __restrict__ W1,
    const float* __restrict__ W2, const float* __restrict__ b2,
    float* __restrict__ out, int write_tail)
{
    __shared__ __align__(16) float sW1b[192];     // W1 rows 64..66
    __shared__ __align__(16) float sH[64 * 68];   // h1, 272B row pitch
    __shared__ float sPart[256];

    const int tid = threadIdx.x;
    if (tid < 192) sW1b[tid] = W1[64 * 64 + tid];

    // W2 column packed into registers: w2p[u] = (W2[2u][f], W2[2u+1][f])
    const int f = tid & 127;
    ull w2p[32];
#pragma unroll
    for (int u = 0; u < 32; u++)
        w2p[u] = pk2(W2[(2 * u) * FOUT_ + f], W2[(2 * u + 1) * FOUT_ + f]);
    const float b2r = b2[f];
    __syncthreads();

    const int n0 = tid >> 2;          // phase-1 neighbor row
    const int hb = (tid & 3) << 4;    // phase-1 h-slice

    float* tail_pos = out + (size_t)BS_ * FOUT_;
    float* tail_bat = out + (size_t)BS_ * FOUT_ + (size_t)BS_ * 3;

    for (int ii = 0; ii < 8; ii++) {
        const int g  = blockIdx.x * 8 + ii;
        const int b  = g >> 10;
        const int c  = g_cnt[g];
        const int ci = g_samp[g];
        const float* P = pos + (size_t)b * N_ * 3;
        const float cx = P[ci * 3 + 0];
        const float cy = P[ci * 3 + 1];
        const float cz = P[ci * 3 + 2];

        // ---- phase 1 ----
        {
            const int jn = g_nbr[g * K_ + ((n0 < c) ? n0 : 0)];
            const float dpx = __fadd_rn(P[jn * 3 + 0], -cx);
            const float dpy = __fadd_rn(P[jn * 3 + 1], -cy);
            const float dpz = __fadd_rn(P[jn * 3 + 2], -cz);

            const ulonglong2* Up =
                (const ulonglong2*)(g_U + (size_t)(b * N_ + jn) * H_ + hb);
            ull acc2[8];
#pragma unroll
            for (int u = 0; u < 4; u++) {
                ulonglong2 v = Up[u];
                acc2[2 * u]     = v.x;
                acc2[2 * u + 1] = v.y;
            }
            const ull mx = pk2(dpx, dpx);
            const ull my = pk2(dpy, dpy);
            const ull mz = pk2(dpz, dpz);
            const ull* wx = (const ull*)(sW1b)       + (hb >> 1);
            const ull* wy = (const ull*)(sW1b + 64)  + (hb >> 1);
            const ull* wz = (const ull*)(sW1b + 128) + (hb >> 1);
#pragma unroll
            for (int u = 0; u < 8; u++) acc2[u] = fma2(mx, wx[u], acc2[u]);
#pragma unroll
            for (int u = 0; u < 8; u++) acc2[u] = fma2(my, wy[u], acc2[u]);
#pragma unroll
            for (int u = 0; u < 8; u++) acc2[u] = fma2(mz, wz[u], acc2[u]);
#pragma unroll
            for (int u = 0; u < 8; u++) {
                float lo, hi;
                upk2(acc2[u], lo, hi);
                float2 o;
                o.x = fmaxf(lo, 0.f);
                o.y = fmaxf(hi, 0.f);
                *(float2*)&sH[n0 * 68 + hb + 2 * u] = o;
            }
        }
        __syncthreads();

        // ---- phase 2 ----
        {
            const int kh = tid >> 7;
            float best = __int_as_float(0xff800000);
            for (int k = kh; k < c; k += 2) {
                const ulonglong2* hv = (const ulonglong2*)(sH + k * 68);
                ull aA = pk2(0.f, 0.f), aB = pk2(0.f, 0.f);
#pragma unroll
                for (int q = 0; q < 16; q++) {
                    ulonglong2 hh = hv[q];
                    aA = fma2(hh.x, w2p[2 * q],     aA);
                    aB = fma2(hh.y, w2p[2 * q + 1], aB);
                }
                ull s2 = add2(aA, aB);
                float lo, hi;
                upk2(s2, lo, hi);
                best = fmaxf(best, __fadd_rn(lo, hi));
            }
            sPart[tid] = best;
            __syncthreads();
            if (tid < 128) {
                float m = fmaxf(sPart[tid], sPart[tid + 128]);
                out[(size_t)g * FOUT_ + f] = (c > 0) ? __fadd_rn(m, b2r) : 0.0f;
            }
            if (write_tail && tid >= 252) {
                int c3 = tid - 252;
                if      (c3 == 0) tail_pos[g * 3 + 0] = cx;
                else if (c3 == 1) tail_pos[g * 3 + 1] = cy;
                else if (c3 == 2) tail_pos[g * 3 + 2] = cz;
                else              tail_bat[g] = (float)b;
            }
        }
        __syncthreads();
    }
}

// ---------------------------------------------------------------------------
extern "C" void kernel_launch(void* const* d_in, const int* in_sizes, int n_in,
                              void* d_out, int out_size) {
    const float *x = nullptr, *pos = nullptr, *W1 = nullptr, *b1 = nullptr,
                *W2 = nullptr, *b2 = nullptr;
    for (int i = 0; i < n_in; i++) {
        switch (in_sizes[i]) {
            case B_ * N_ * FIN_:  x   = (const float*)d_in[i]; break;
            case B_ * N_ * 3:     pos = (const float*)d_in[i]; break;
            case (FIN_ + 3) * H_: W1  = (const float*)d_in[i]; break;
            case H_:              b1  = (const float*)d_in[i]; break;
            case H_ * FOUT_:      W2  = (const float*)d_in[i]; break;
            case FOUT_:           b2  = (const float*)d_in[i]; break;
            default: break; // batch ids reconstructed analytically
        }
    }
    float* out = (float*)d_out;

    const int total3 = BS_ * FOUT_ + BS_ * 3 + BS_;
    const int tail = (out_size >= total3) ? 1 : 0;

    u_kernel<<<(B_ * N_) / 64, 256>>>(x, W1, b1);

    const int fps_smem = (3 * N_ + 64) * 4;   // 49408 B
    cudaFuncSetAttribute(fps_kernel,
                         cudaFuncAttributeMaxDynamicSharedMemorySize, fps_smem);
    fps_kernel<<<B_, 512, fps_smem>>>(pos);

    radius_kernel<<<BS_ / 8, 256>>>(pos);

    mlp_kernel<<<BS_ / 8, 256>>>(pos, W1, W2, b2, out, tail);
}

// round 10
// speedup vs baseline: 2.4186x; 1.2460x over previous
#include <cuda_runtime.h>
#include <cstdint>

#define B_    8
#define N_    4096
#define FIN_  64
#define S_    1024
#define K_    64
#define H_    64
#define FOUT_ 128
#define BS_   (B_*S_)
#define CH    128              // samples per pipeline chunk
#define NCHUNK (S_/CH)         // 8
#define WBLK  256              // worker blocks per pipe stage
#define TPW   4                // centroids (tiles) per worker block

typedef unsigned long long ull;

// Device-global scratch. All locations written before read within each run
// (and rewritten every run) -> replay-deterministic, no reset needed.
__device__ int g_samp[BS_];
__device__ float g_dist[B_ * N_];
__device__ __align__(16) float g_U[(size_t)B_ * N_ * H_];

// Squared distance with the reference's exact f32 associativity.
__device__ __forceinline__ float sqd(float ax, float ay, float az,
                                     float bx, float by, float bz) {
    float dx = __fadd_rn(ax, -bx);
    float dy = __fadd_rn(ay, -by);
    float dz = __fadd_rn(az, -bz);
    return __fadd_rn(__fadd_rn(__fmul_rn(dx, dx), __fmul_rn(dy, dy)),
                     __fmul_rn(dz, dz));
}

// Packed f32x2 helpers. Per-lane rounding identical to scalar __fadd_rn etc.
__device__ __forceinline__ ull pk2(float lo, float hi) {
    ull r; asm("mov.b64 %0, {%1, %2};" : "=l"(r) : "f"(lo), "f"(hi)); return r;
}
__device__ __forceinline__ ull add2(ull a, ull b) {
    ull r; asm("add.rn.f32x2 %0, %1, %2;" : "=l"(r) : "l"(a), "l"(b)); return r;
}
__device__ __forceinline__ ull mul2(ull a, ull b) {
    ull r; asm("mul.rn.f32x2 %0, %1, %2;" : "=l"(r) : "l"(a), "l"(b)); return r;
}
__device__ __forceinline__ ull fma2(ull a, ull b, ull c) {
    ull r; asm("fma.rn.f32x2 %0, %1, %2, %3;" : "=l"(r) : "l"(a), "l"(b), "l"(c)); return r;
}
__device__ __forceinline__ void upk2(ull p, float& lo, float& hi) {
    asm("mov.b64 {%0, %1}, %2;" : "=f"(lo), "=f"(hi) : "l"(p));
}

// ---------------------------------------------------------------------------
// Kernel A: U'[j][h] = b1[h] + sum_{cf=0..63} x[j][cf] * W1[cf][h]  (proven)
// ---------------------------------------------------------------------------
__global__ __launch_bounds__(256) void u_kernel(
    const float* __restrict__ x, const float* __restrict__ W1,
    const float* __restrict__ b1)
{
    __shared__ __align__(16) float sW[64 * 64];
    __shared__ __align__(16) float sB[64];
    __shared__ __align__(16) float sX[64 * 68];

    const int tid = threadIdx.x;
    const int r0  = blockIdx.x * 64;

    for (int i = tid; i < 64 * 64; i += 256) sW[i] = W1[i];
    if (tid < 64) sB[tid] = b1[tid];
    for (int e = tid; e < 64 * 64; e += 256) {
        int row = e >> 6, cf = e & 63;
        sX[row * 68 + cf] = x[(size_t)(r0 + row) * FIN_ + cf];
    }
    __syncthreads();

    const int n0 = tid >> 2;
    const int hb = (tid & 3) << 4;

    ull acc2[8];
#pragma unroll
    for (int u = 0; u < 8; u++)
        acc2[u] = pk2(sB[hb + 2 * u], sB[hb + 2 * u + 1]);

    const ull* Wp = (const ull*)sW;
    for (int cf = 0; cf < 64; cf++) {
        float m = sX[n0 * 68 + cf];
        ull mm = pk2(m, m);
        const ull* wrow = Wp + cf * 32 + (hb >> 1);
#pragma unroll
        for (int u = 0; u < 8; u++)
            acc2[u] = fma2(mm, wrow[u], acc2[u]);
    }

    float* Urow = g_U + (size_t)(r0 + n0) * H_ + hb;
#pragma unroll
    for (int u = 0; u < 8; u++) {
        float lo, hi;
        upk2(acc2[u], lo, hi);
        float2 o; o.x = lo; o.y = hi;
        *(float2*)(Urow + 2 * u) = o;
    }
}

// ---------------------------------------------------------------------------
// FPS role (R3-proven 256-thread / 16-pt body + chunk entry/exit).
// Processes iterations [s0, s1); dist state persisted in g_dist between
// chunks. s0==0 additionally emits sample 0 and the init distance pass.
// ---------------------------------------------------------------------------
__device__ void fps_role(const float* __restrict__ pos, int b, float* fsm,
                         int s0, int s1)
{
    const int t = threadIdx.x;
    float* sx = fsm;
    float* sy = fsm + N_;
    float* sz = fsm + 2 * N_;
    ull* skey = (ull*)(fsm + 3 * N_);   // 16 entries (8 warps, double buffered)

    const float* P = pos + (size_t)b * N_ * 3;

    for (int e = t; e < N_ * 3; e += 256) {
        float v = P[e];
        int p = e / 3, c = e - p * 3;
        if (c == 0) sx[p] = v; else if (c == 1) sy[p] = v; else sz[p] = v;
    }
    __syncthreads();

    const int base = t * 16;
    ull px[8], py[8], pz[8];
#pragma unroll
    for (int i = 0; i < 8; i++) {
        px[i] = pk2(sx[base + 2 * i], sx[base + 2 * i + 1]);
        py[i] = pk2(sy[base + 2 * i], sy[base + 2 * i + 1]);
        pz[i] = pk2(sz[base + 2 * i], sz[base + 2 * i + 1]);
    }

    float dist[16];
    int itstart;
    if (s0 == 0) {
        ull nqx = pk2(-sx[0], -sx[0]);
        ull nqy = pk2(-sy[0], -sy[0]);
        ull nqz = pk2(-sz[0], -sz[0]);
#pragma unroll
        for (int i = 0; i < 8; i++) {
            ull dx = add2(px[i], nqx);
            ull dy = add2(py[i], nqy);
            ull dz = add2(pz[i], nqz);
            ull s = add2(add2(mul2(dx, dx), mul2(dy, dy)), mul2(dz, dz));
            upk2(s, dist[2 * i], dist[2 * i + 1]);
        }
        if (t == 0) g_samp[b * S_] = 0;
        itstart = 1;
    } else {
#pragma unroll
        for (int i = 0; i < 16; i++) dist[i] = g_dist[b * N_ + base + i];
        itstart = s0;
    }

    const int lane = t & 31;
    const int wid  = t >> 5;

    for (int it = itstart; it < s1; it++) {
        // per-thread max tree (value only)
        float m0 = fmaxf(dist[0], dist[1]),   m1 = fmaxf(dist[2], dist[3]);
        float m2 = fmaxf(dist[4], dist[5]),   m3 = fmaxf(dist[6], dist[7]);
        float m4 = fmaxf(dist[8], dist[9]),   m5 = fmaxf(dist[10], dist[11]);
        float m6 = fmaxf(dist[12], dist[13]), m7 = fmaxf(dist[14], dist[15]);
        m0 = fmaxf(m0, m1); m2 = fmaxf(m2, m3); m4 = fmaxf(m4, m5); m6 = fmaxf(m6, m7);
        m0 = fmaxf(m0, m2); m4 = fmaxf(m4, m6);
        const float lm = fmaxf(m0, m4);

        const float wm = __uint_as_float(
            __reduce_max_sync(0xFFFFFFFFu, __float_as_uint(lm)));

        unsigned ball = __ballot_sync(0xFFFFFFFFu, lm == wm);
        int src = __ffs(ball) - 1;
        int li = 0;
#pragma unroll
        for (int i = 15; i >= 0; i--) if (dist[i] == wm) li = i;
        int gidx = __shfl_sync(0xFFFFFFFFu, base + li, src);

        const int buf = (it & 1) << 3;
        if (lane == 0)
            skey[buf + wid] = (((ull)__float_as_uint(wm)) << 32)
                              | (unsigned)(0xFFFFFFFFu - (unsigned)gidx);
        __syncthreads();

        ull k0 = skey[buf + 0], k1 = skey[buf + 1];
        ull k2 = skey[buf + 2], k3 = skey[buf + 3];
        ull k4 = skey[buf + 4], k5 = skey[buf + 5];
        ull k6 = skey[buf + 6], k7 = skey[buf + 7];
        k0 = (k1 > k0) ? k1 : k0;  k2 = (k3 > k2) ? k3 : k2;
        k4 = (k5 > k4) ? k5 : k4;  k6 = (k7 > k6) ? k7 : k6;
        k0 = (k2 > k0) ? k2 : k0;  k4 = (k6 > k4) ? k6 : k4;
        k0 = (k4 > k0) ? k4 : k0;
        const int widx =
            ((int)(0xFFFFFFFFu - (unsigned)(k0 & 0xFFFFFFFFull))) & (N_ - 1);

        if (t == 0) g_samp[b * S_ + it] = widx;

        const float qx = sx[widx], qy = sy[widx], qz = sz[widx];
        ull nqx = pk2(-qx, -qx);
        ull nqy = pk2(-qy, -qy);
        ull nqz = pk2(-qz, -qz);
#pragma unroll
        for (int i = 0; i < 8; i++) {
            ull dx = add2(px[i], nqx);
            ull dy = add2(py[i], nqy);
            ull dz = add2(pz[i], nqz);
            ull s = add2(add2(mul2(dx, dx), mul2(dy, dy)), mul2(dz, dz));
            float lo, hi;
            upk2(s, lo, hi);
            dist[2 * i]     = fminf(dist[2 * i], lo);
            dist[2 * i + 1] = fminf(dist[2 * i + 1], hi);
        }
    }

#pragma unroll
    for (int i = 0; i < 16; i++) g_dist[b * N_ + base + i] = dist[i];
}

// ---------------------------------------------------------------------------
// Worker role: radius (R9 warp code, lists in SMEM) + MLP (R9 exact code)
// for TPW centroids of chunk [ws0, ws0+CH). Reads only state written by
// PREVIOUS kernels (g_samp, g_U) -> no intra-kernel communication.
// Worker SMEM layout (floats): sW1b 192 | sH 4352 | sPart 256 | snbr 256(int)
//                              | scnt 4(int) | scx 4 | scy 4 | scz 4
// ---------------------------------------------------------------------------
__device__ void worker_role(const float* __restrict__ pos,
                            const float* __restrict__ W1,
                            const float* __restrict__ W2,
                            const float* __restrict__ b2,
                            float* __restrict__ out, int write_tail,
                            int ws0, float* sm_)
{
    float* sW1b = sm_;                  // 192
    float* sH   = sm_ + 192;            // 4352 (row pitch 68)
    float* sPart= sm_ + 192 + 4352;     // 256
    int*   snbr = (int*)(sPart + 256);  // TPW*64
    int*   scnt = snbr + TPW * K_;      // TPW
    float* scx  = (float*)(scnt + TPW);
    float* scy  = scx + TPW;
    float* scz  = scy + TPW;

    const int tid = threadIdx.x;
    for (int i = tid; i < 192; i += 256) sW1b[i] = W1[64 * 64 + i];

    const int f = tid & 127;
    ull w2p[32];
#pragma unroll
    for (int u = 0; u < 32; u++)
        w2p[u] = pk2(W2[(2 * u) * FOUT_ + f], W2[(2 * u + 1) * FOUT_ + f]);
    const float b2r = b2[f];

    const int lane = tid & 31;
    const int w    = tid >> 5;
    const int bw   = blockIdx.x - B_;
    const float r2 = (float)(0.2 * 0.2);

    // ---- radius: warps 0..TPW-1, one centroid each (R9-proven body) ----
    if (w < TPW) {
        const int ci_idx = bw * TPW + w;
        const int b    = ci_idx >> 7;              // 128 sidx per cloud per chunk
        const int sidx = ws0 + (ci_idx & 127);
        const int g    = b * S_ + sidx;
        const int ci   = g_samp[g];
        const float* P = pos + (size_t)b * N_ * 3;
        const float cx = P[ci * 3 + 0];
        const float cy = P[ci * 3 + 1];
        const float cz = P[ci * 3 + 2];

        int cnt = 0;
        for (int j0 = 0; j0 < N_ && cnt < K_; j0 += 32) {
            int j = j0 + lane;
            float d2 = sqd(cx, cy, cz, P[j*3+0], P[j*3+1], P[j*3+2]);
            bool iw = (d2 <= r2);
            unsigned m = __ballot_sync(0xFFFFFFFFu, iw);
            int rank = __popc(m & ((1u << lane) - 1u));
            if (iw && (cnt + rank) < K_) snbr[w * K_ + cnt + rank] = j;
            cnt += __popc(m);
        }
        if (lane == 0) {
            scnt[w] = (cnt < K_) ? cnt : K_;
            scx[w] = cx; scy[w] = cy; scz[w] = cz;
        }
    }
    __syncthreads();

    const int n0 = tid >> 2;
    const int hb = (tid & 3) << 4;

    float* tail_pos = out + (size_t)BS_ * FOUT_;
    float* tail_bat = out + (size_t)BS_ * FOUT_ + (size_t)BS_ * 3;

    for (int ii = 0; ii < TPW; ii++) {
        const int ci_idx = bw * TPW + ii;
        const int b    = ci_idx >> 7;
        const int sidx = ws0 + (ci_idx & 127);
        const int g    = b * S_ + sidx;
        const int c    = scnt[ii];
        const float cx = scx[ii], cy = scy[ii], cz = scz[ii];
        const float* P = pos + (size_t)b * N_ * 3;

        // ---- phase 1 (R9 exact) ----
        {
            const int jn = snbr[ii * K_ + ((n0 < c) ? n0 : 0)];
            const float dpx = __fadd_rn(P[jn * 3 + 0], -cx);
            const float dpy = __fadd_rn(P[jn * 3 + 1], -cy);
            const float dpz = __fadd_rn(P[jn * 3 + 2], -cz);

            const ulonglong2* Up =
                (const ulonglong2*)(g_U + (size_t)(b * N_ + jn) * H_ + hb);
            ull acc2[8];
#pragma unroll
            for (int u = 0; u < 4; u++) {
                ulonglong2 v = Up[u];
                acc2[2 * u]     = v.x;
                acc2[2 * u + 1] = v.y;
            }
            const ull mx = pk2(dpx, dpx);
            const ull my = pk2(dpy, dpy);
            const ull mz = pk2(dpz, dpz);
            const ull* wx = (const ull*)(sW1b)       + (hb >> 1);
            const ull* wy = (const ull*)(sW1b + 64)  + (hb >> 1);
            const ull* wz = (const ull*)(sW1b + 128) + (hb >> 1);
#pragma unroll
            for (int u = 0; u < 8; u++) acc2[u] = fma2(mx, wx[u], acc2[u]);
#pragma unroll
            for (int u = 0; u < 8; u++) acc2[u] = fma2(my, wy[u], acc2[u]);
#pragma unroll
            for (int u = 0; u < 8; u++) acc2[u] = fma2(mz, wz[u], acc2[u]);
#pragma unroll
            for (int u = 0; u < 8; u++) {
                float lo, hi;
                upk2(acc2[u], lo, hi);
                float2 o;
                o.x = fmaxf(lo, 0.f);
                o.y = fmaxf(hi, 0.f);
                *(float2*)&sH[n0 * 68 + hb + 2 * u] = o;
            }
        }
        __syncthreads();

        // ---- phase 2 (R9 exact) ----
        {
            const int kh = tid >> 7;
            float best = __int_as_float(0xff800000);
            for (int k = kh; k < c; k += 2) {
                const ulonglong2* hv = (const ulonglong2*)(sH + k * 68);
                ull aA = pk2(0.f, 0.f), aB = pk2(0.f, 0.f);
#pragma unroll
                for (int q = 0; q < 16; q++) {
                    ulonglong2 hh = hv[q];
                    aA = fma2(hh.x, w2p[2 * q],     aA);
                    aB = fma2(hh.y, w2p[2 * q + 1], aB);
                }
                ull s2 = add2(aA, aB);
                float lo, hi;
                upk2(s2, lo, hi);
                best = fmaxf(best, __fadd_rn(lo, hi));
            }
            sPart[tid] = best;
            __syncthreads();
            if (tid < 128) {
                float m = fmaxf(sPart[tid], sPart[tid + 128]);
                out[(size_t)g * FOUT_ + f] = (c > 0) ? __fadd_rn(m, b2r) : 0.0f;
            }
            if (write_tail && tid >= 252) {
                int c3 = tid - 252;
                if      (c3 == 0) tail_pos[g * 3 + 0] = cx;
                else if (c3 == 1) tail_pos[g * 3 + 1] = cy;
                else if (c3 == 2) tail_pos[g * 3 + 2] = cz;
                else              tail_bat[g] = (float)b;
            }
        }
        __syncthreads();
    }
}

// ---------------------------------------------------------------------------
// Pipe kernel: blocks 0..7 run FPS chunk [fs0, fs1); blocks 8.. run
// radius+MLP for chunk [ws0, ws0+CH). All producer->consumer edges cross
// kernel boundaries; there is NO intra-kernel communication.
// ---------------------------------------------------------------------------
#define SMEM_BYTES ((3 * N_ + 32) * 4)   // 49280 (fps role; worker uses less)

__global__ __launch_bounds__(256) void pipe_kernel(
    const float* __restrict__ pos, const float* __restrict__ W1,
    const float* __restrict__ W2, const float* __restrict__ b2,
    float* __restrict__ out, int write_tail, int fs0, int fs1, int ws0)
{
    extern __shared__ __align__(16) float sm[];
    const int bid = blockIdx.x;
    if (bid < B_) {
        if (fs0 < S_) fps_role(pos, bid, sm, fs0, fs1);
        return;
    }
    if (ws0 >= 0)
        worker_role(pos, W1, W2, b2, out, write_tail, ws0, sm);
}

// ---------------------------------------------------------------------------
extern "C" void kernel_launch(void* const* d_in, const int* in_sizes, int n_in,
                              void* d_out, int out_size) {
    const float *x = nullptr, *pos = nullptr, *W1 = nullptr, *b1 = nullptr,
                *W2 = nullptr, *b2 = nullptr;
    for (int i = 0; i < n_in; i++) {
        switch (in_sizes[i]) {
            case B_ * N_ * FIN_:  x   = (const float*)d_in[i]; break;
            case B_ * N_ * 3:     pos = (const float*)d_in[i]; break;
            case (FIN_ + 3) * H_: W1  = (const float*)d_in[i]; break;
            case H_:              b1  = (const float*)d_in[i]; break;
            case H_ * FOUT_:      W2  = (const float*)d_in[i]; break;
            case FOUT_:           b2  = (const float*)d_in[i]; break;
            default: break; // batch ids reconstructed analytically
        }
    }
    float* out = (float*)d_out;

    const int total3 = BS_ * FOUT_ + BS_ * 3 + BS_;
    const int tail = (out_size >= total3) ? 1 : 0;

    u_kernel<<<(B_ * N_) / 64, 256>>>(x, W1, b1);

    cudaFuncSetAttribute(pipe_kernel,
                         cudaFuncAttributeMaxDynamicSharedMemorySize, SMEM_BYTES);

    for (int p = 0; p <= NCHUNK; p++) {
        const int fs0 = p * CH;
        const int fs1 = fs0 + CH;
        const int ws0 = (p - 1) * CH;
        const int grid = (p == 0) ? B_ : (B_ + WBLK);
        pipe_kernel<<<grid, 256, SMEM_BYTES>>>(pos, W1, W2, b2, out, tail,
                                               fs0, fs1, ws0);
    }
}